// round 3
// baseline (speedup 1.0000x reference)
#include <cuda_runtime.h>
#include <math.h>

#define B 32
#define T 128
#define BT 4096
#define E 1024
#define H 1024
#define G 4096
#define V 32000
#define HP 1028   // padded h row length in smem (float4-aligned, low-conflict)

// ---------------- device scratch (no allocations allowed) ----------------
__device__ __align__(16) float g_xemb[BT * E];     // 16 MB embedded inputs
__device__ __align__(16) float g_gx[BT * G];       // 64 MB input-path gates (reused per layer)
__device__ __align__(16) float g_hseq0[BT * H];    // 16 MB layer-0 outputs
__device__ __align__(16) float g_hseq1[BT * H];    // 16 MB layer-1 outputs
__device__ __align__(16) float g_h0[B * H];
__device__ __align__(16) float g_h1[B * H];
__device__ __align__(16) float g_c[B * H];

// ---------------- embedding gather ----------------
__global__ void embed_kernel(const int* __restrict__ idx, const float* __restrict__ emb) {
    int row = blockIdx.x;                       // row = b*T + t
    int tok = idx[row];
    const float4* src = (const float4*)(emb + (size_t)tok * E);
    float4* dst = (float4*)(g_xemb + (size_t)row * E);
    dst[threadIdx.x] = src[threadIdx.x];        // 256 threads * 4 = 1024 floats
}

__global__ void zero_state_kernel() {
    int i = blockIdx.x * blockDim.x + threadIdx.x;
    if (i < B * H) { g_h0[i] = 0.f; g_c[i] = 0.f; }
}

// ---------------- classic 128x128x8 register-tiled SGEMM + bias ----------------
// C[M,N] = A[M,K] @ Bm[K,N] + bias[N];  M,N multiples of 128, K multiple of 8.
__global__ __launch_bounds__(256) void sgemm_bias(
    const float* __restrict__ A, const float* __restrict__ Bm,
    const float* __restrict__ bias, float* __restrict__ C,
    int M, int N, int K)
{
    __shared__ float As[8][128];
    __shared__ float Bs[8][128];
    int tid = threadIdx.x;
    int bx = blockIdx.x, by = blockIdx.y;
    int tx = tid & 15, ty = tid >> 4;

    const float* Ab = A + (size_t)by * 128 * K;
    const float* Bb = Bm + (size_t)bx * 128;

    int arow = tid >> 1, acol = (tid & 1) * 4;
    int brow = tid >> 5, bcol = (tid & 31) * 4;

    float acc[8][8];
#pragma unroll
    for (int i = 0; i < 8; i++)
#pragma unroll
        for (int j = 0; j < 8; j++) acc[i][j] = 0.f;

    for (int kt = 0; kt < K; kt += 8) {
        float4 av = *(const float4*)(Ab + (size_t)arow * K + kt + acol);
        float4 bv = *(const float4*)(Bb + (size_t)(kt + brow) * N + bcol);
        __syncthreads();
        As[acol + 0][arow] = av.x;
        As[acol + 1][arow] = av.y;
        As[acol + 2][arow] = av.z;
        As[acol + 3][arow] = av.w;
        *(float4*)&Bs[brow][bcol] = bv;
        __syncthreads();
#pragma unroll
        for (int k = 0; k < 8; k++) {
            float ar[8], br[8];
            *(float4*)&ar[0] = *(const float4*)&As[k][ty * 8];
            *(float4*)&ar[4] = *(const float4*)&As[k][ty * 8 + 4];
            *(float4*)&br[0] = *(const float4*)&Bs[k][tx * 8];
            *(float4*)&br[4] = *(const float4*)&Bs[k][tx * 8 + 4];
#pragma unroll
            for (int i = 0; i < 8; i++)
#pragma unroll
                for (int j = 0; j < 8; j++)
                    acc[i][j] = fmaf(ar[i], br[j], acc[i][j]);
        }
    }

#pragma unroll
    for (int i = 0; i < 8; i++) {
        int row = by * 128 + ty * 8 + i;
        int col = bx * 128 + tx * 8;
        float* Cp = C + (size_t)row * N + col;
        const float* bp = bias + col;
        float4 o0, o1;
        o0.x = acc[i][0] + bp[0]; o0.y = acc[i][1] + bp[1];
        o0.z = acc[i][2] + bp[2]; o0.w = acc[i][3] + bp[3];
        o1.x = acc[i][4] + bp[4]; o1.y = acc[i][5] + bp[5];
        o1.z = acc[i][6] + bp[6]; o1.w = acc[i][7] + bp[7];
        *(float4*)Cp = o0;
        *(float4*)(Cp + 4) = o1;
    }
}

// ---------------- fused LSTM timestep ----------------
// Block = 8 hidden units (j0..j0+7) x 4 gates x 32 batches, split-K=4 in-block.
// gates(b,col) = gx[(b*T+t), col] + sum_k h_in[b,k] * Wh[k, col], then cell update.
#define FMA4(ai, hv, wv)                                   \
    acc[ai][0] = fmaf(hv, wv.x, acc[ai][0]);               \
    acc[ai][1] = fmaf(hv, wv.y, acc[ai][1]);               \
    acc[ai][2] = fmaf(hv, wv.z, acc[ai][2]);               \
    acc[ai][3] = fmaf(hv, wv.w, acc[ai][3]);

__global__ __launch_bounds__(256) void lstm_step(
    const float* __restrict__ gx,     // [BT][G] input-path gates (+bias)
    const float* __restrict__ Wh,     // [H][G] recurrent weight slice
    const float* __restrict__ h_in,   // [B][H]
    float* __restrict__ h_out,        // [B][H]
    float* __restrict__ c_st,         // [B][H]
    float* __restrict__ hseq,         // [BT][H]
    int t)
{
    extern __shared__ float sm[];
    float* h_sm  = sm;                    // 32 * HP
    float* red   = sm + 32 * HP;          // 3 * 1024 split-K partials
    float* gates = red + 3 * 1024;        // 32 * 33

    int tid = threadIdx.x;

    // stage h into smem (coalesced float4 copy)
    const float4* h4 = (const float4*)h_in;
#pragma unroll
    for (int it = 0; it < 32; it++) {
        int q = tid + it * 256;           // 0..8191
        int b = q >> 8, k4 = q & 255;
        float4 v = h4[q];
        *(float4*)&h_sm[b * HP + k4 * 4] = v;
    }
    __syncthreads();

    int ks = tid >> 6;                    // k-slice 0..3
    int r  = tid & 63;
    int bg = r >> 3;                      // batch group 0..7 (4 batches each)
    int cq = r & 7;                       // column quad 0..7
    int g  = cq >> 1;                     // gate 0..3 (i,j,f,o)
    int jo4 = (cq & 1) * 4;               // j offset within the 8-unit tile
    int j0 = blockIdx.x * 8;

    const float4* W4 = (const float4*)Wh + ((g * H + j0 + jo4) >> 2);
    const float* hb0p = &h_sm[(bg * 4 + 0) * HP];
    const float* hb1p = &h_sm[(bg * 4 + 1) * HP];
    const float* hb2p = &h_sm[(bg * 4 + 2) * HP];
    const float* hb3p = &h_sm[(bg * 4 + 3) * HP];

    float acc[4][4];
#pragma unroll
    for (int i = 0; i < 4; i++)
#pragma unroll
        for (int j = 0; j < 4; j++) acc[i][j] = 0.f;

    int k0 = ks * 256;
#pragma unroll 2
    for (int k = k0; k < k0 + 256; k += 4) {
        float4 w0 = W4[(size_t)(k + 0) * (G / 4)];
        float4 w1 = W4[(size_t)(k + 1) * (G / 4)];
        float4 w2 = W4[(size_t)(k + 2) * (G / 4)];
        float4 w3 = W4[(size_t)(k + 3) * (G / 4)];
        float4 ha = *(const float4*)&hb0p[k];
        float4 hb = *(const float4*)&hb1p[k];
        float4 hc = *(const float4*)&hb2p[k];
        float4 hd = *(const float4*)&hb3p[k];
        FMA4(0, ha.x, w0) FMA4(1, hb.x, w0) FMA4(2, hc.x, w0) FMA4(3, hd.x, w0)
        FMA4(0, ha.y, w1) FMA4(1, hb.y, w1) FMA4(2, hc.y, w1) FMA4(3, hd.y, w1)
        FMA4(0, ha.z, w2) FMA4(1, hb.z, w2) FMA4(2, hc.z, w2) FMA4(3, hd.z, w2)
        FMA4(0, ha.w, w3) FMA4(1, hb.w, w3) FMA4(2, hc.w, w3) FMA4(3, hd.w, w3)
    }

    // split-K reduction
    if (ks > 0) {
#pragma unroll
        for (int i = 0; i < 4; i++)
#pragma unroll
            for (int j = 0; j < 4; j++)
                red[(ks - 1) * 1024 + r * 16 + i * 4 + j] = acc[i][j];
    }
    __syncthreads();
    if (ks == 0) {
#pragma unroll
        for (int i = 0; i < 4; i++)
#pragma unroll
            for (int j = 0; j < 4; j++) {
                int cell = r * 16 + i * 4 + j;
                float v = acc[i][j] + red[cell] + red[1024 + cell] + red[2048 + cell];
                int b = bg * 4 + i;
                gates[b * 33 + g * 8 + jo4 + j] = v;
            }
    }
    __syncthreads();

    // fused cell update: thread -> (b, j)
    {
        int b = tid >> 3;
        int j = tid & 7;
        int jg = j0 + j;
        const float* gxr = gx + (size_t)(b * T + t) * G;
        float vi = gates[b * 33 +  0 + j] + gxr[0 * H + jg];
        float vj = gates[b * 33 +  8 + j] + gxr[1 * H + jg];
        float vf = gates[b * 33 + 16 + j] + gxr[2 * H + jg];
        float vo = gates[b * 33 + 24 + j] + gxr[3 * H + jg];
        float cold = c_st[b * H + jg];
        float si = 1.f / (1.f + expf(-vi));
        float sf = 1.f / (1.f + expf(-(vf + 1.f)));
        float so = 1.f / (1.f + expf(-vo));
        float cnew = sf * cold + si * tanhf(vj);
        float hnew = so * tanhf(cnew);
        c_st[b * H + jg] = cnew;
        h_out[b * H + jg] = hnew;
        hseq[(size_t)(b * T + t) * H + jg] = hnew;
    }
}

// ---------------- launcher ----------------
extern "C" void kernel_launch(void* const* d_in, const int* in_sizes, int n_in,
                              void* d_out, int out_size)
{
    const int*   input_seq = (const int*)d_in[0];
    const float* emb = (const float*)d_in[1];
    const float* W0  = (const float*)d_in[2];
    const float* b0  = (const float*)d_in[3];
    const float* W1  = (const float*)d_in[4];
    const float* b1  = (const float*)d_in[5];
    const float* Wd  = (const float*)d_in[6];
    const float* bd  = (const float*)d_in[7];
    float* out = (float*)d_out;
    (void)in_sizes; (void)n_in; (void)out_size;

    float *xemb, *gx, *hs0, *hs1, *h0, *h1, *cbuf;
    cudaGetSymbolAddress((void**)&xemb, g_xemb);
    cudaGetSymbolAddress((void**)&gx,   g_gx);
    cudaGetSymbolAddress((void**)&hs0,  g_hseq0);
    cudaGetSymbolAddress((void**)&hs1,  g_hseq1);
    cudaGetSymbolAddress((void**)&h0,   g_h0);
    cudaGetSymbolAddress((void**)&h1,   g_h1);
    cudaGetSymbolAddress((void**)&cbuf, g_c);

    size_t smem = (size_t)(32 * HP + 3 * 1024 + 32 * 33) * sizeof(float);
    cudaFuncSetAttribute(lstm_step, cudaFuncAttributeMaxDynamicSharedMemorySize, (int)smem);

    // 1) embedding
    embed_kernel<<<BT, 256>>>(input_seq, emb);

    // 2) layer-0 input-path gates: GX = Xemb @ W0[0:E] + b0
    dim3 gGX(G / 128, BT / 128);
    sgemm_bias<<<gGX, 256>>>(xemb, W0, b0, gx, BT, G, E);

    // 3) layer-0 recurrence
    zero_state_kernel<<<(B * H + 255) / 256, 256>>>();
    for (int t = 0; t < T; t++) {
        float* hin  = (t & 1) ? h1 : h0;
        float* hout = (t & 1) ? h0 : h1;
        lstm_step<<<128, 256, smem>>>(gx, W0 + (size_t)E * G, hin, hout, cbuf, hs0, t);
    }

    // 4) layer-1 input-path gates: GX = hseq0 @ W1[0:H] + b1
    sgemm_bias<<<gGX, 256>>>(hs0, W1, b1, gx, BT, G, H);

    // 5) layer-1 recurrence
    zero_state_kernel<<<(B * H + 255) / 256, 256>>>();
    for (int t = 0; t < T; t++) {
        float* hin  = (t & 1) ? h1 : h0;
        float* hout = (t & 1) ? h0 : h1;
        lstm_step<<<128, 256, smem>>>(gx, W1 + (size_t)H * G, hin, hout, cbuf, hs1, t);
    }

    // 6) dense projection: out = hseq1 @ Wd + bd
    dim3 gOUT(V / 128, BT / 128);
    sgemm_bias<<<gOUT, 256>>>(hs1, Wd, bd, out, BT, V, H);
}

// round 4
// speedup vs baseline: 1.2253x; 1.2253x over previous
#include <cuda_runtime.h>
#include <math.h>

#define B 32
#define T 128
#define BT 4096
#define E 1024
#define H 1024
#define G 4096
#define V 32000

typedef unsigned long long ull;

// ---------------- packed f32x2 helpers (sm_103a FFMA2 path) ----------------
__device__ __forceinline__ ull fma2(ull a, ull b, ull c) {
    ull d;
    asm("fma.rn.f32x2 %0, %1, %2, %3;" : "=l"(d) : "l"(a), "l"(b), "l"(c));
    return d;
}
__device__ __forceinline__ ull splat2(float x) {
    ull d;
    asm("mov.b64 %0, {%1, %1};" : "=l"(d) : "f"(x));
    return d;
}
__device__ __forceinline__ void unpack2(ull v, float& lo, float& hi) {
    asm("mov.b64 {%0, %1}, %2;" : "=f"(lo), "=f"(hi) : "l"(v));
}

// ---------------- cp.async helpers ----------------
__device__ __forceinline__ void cp_async16(void* smem_ptr, const void* gptr) {
    unsigned s = (unsigned)__cvta_generic_to_shared(smem_ptr);
    asm volatile("cp.async.cg.shared.global [%0], [%1], 16;\n" :: "r"(s), "l"(gptr));
}
__device__ __forceinline__ void cp_async_commit() {
    asm volatile("cp.async.commit_group;\n");
}
__device__ __forceinline__ void cp_async_wait_all() {
    asm volatile("cp.async.wait_group 0;\n" ::: "memory");
}

// ---------------- device scratch ----------------
__device__ __align__(16) float g_xemb[BT * E];
__device__ __align__(16) float g_gx[BT * G];
__device__ __align__(16) float g_hseq0[BT * H];
__device__ __align__(16) float g_hseq1[BT * H];
__device__ __align__(16) float g_h0[B * H];
__device__ __align__(16) float g_h1[B * H];
__device__ __align__(16) float g_c[B * H];

// ---------------- embedding gather ----------------
__global__ void embed_kernel(const int* __restrict__ idx, const float* __restrict__ emb) {
    int row = blockIdx.x;
    int tok = idx[row];
    const float4* src = (const float4*)(emb + (size_t)tok * E);
    float4* dst = (float4*)(g_xemb + (size_t)row * E);
    dst[threadIdx.x] = src[threadIdx.x];
}

__global__ void zero_state_kernel() {
    int i = blockIdx.x * blockDim.x + threadIdx.x;
    if (i < B * H) { g_h0[i] = 0.f; g_c[i] = 0.f; }
}

// ---------------- double-buffered FFMA2 SGEMM + bias ----------------
// C[M,N] = A[M,K] @ Bm[K,N] + bias[N]; M,N mult of 128, K mult of 8.
__global__ __launch_bounds__(256, 2) void sgemm_bias2(
    const float* __restrict__ A, const float* __restrict__ Bm,
    const float* __restrict__ bias, float* __restrict__ C,
    int M, int N, int K)
{
    __shared__ float As[2][8][128];
    __shared__ float Bs[2][8][128];
    int tid = threadIdx.x;
    int bx = blockIdx.x, by = blockIdx.y;
    int tx = tid & 15, ty = tid >> 4;

    const float* Ab = A + (size_t)by * 128 * K;
    const float* Bb = Bm + (size_t)bx * 128;

    int arow = tid >> 1, acol = (tid & 1) * 4;
    int brow = tid >> 5, bcol = (tid & 31) * 4;

    ull acc[8][4];
#pragma unroll
    for (int i = 0; i < 8; i++)
#pragma unroll
        for (int p = 0; p < 4; p++) acc[i][p] = 0ull;

    // prologue: tile 0
    {
        float4 av = *(const float4*)(Ab + (size_t)arow * K + acol);
        float4 bv = *(const float4*)(Bb + (size_t)brow * N + bcol);
        As[0][acol + 0][arow] = av.x;
        As[0][acol + 1][arow] = av.y;
        As[0][acol + 2][arow] = av.z;
        As[0][acol + 3][arow] = av.w;
        *(float4*)&Bs[0][brow][bcol] = bv;
    }
    __syncthreads();

    int nk = K >> 3;
    for (int kt = 0; kt < nk; kt++) {
        int cur = kt & 1;
        float4 av, bv;
        bool more = (kt + 1 < nk);
        if (more) {
            av = *(const float4*)(Ab + (size_t)arow * K + (kt + 1) * 8 + acol);
            bv = *(const float4*)(Bb + (size_t)((kt + 1) * 8 + brow) * N + bcol);
        }
#pragma unroll
        for (int k = 0; k < 8; k++) {
            float ar[8];
            *(float4*)&ar[0] = *(const float4*)&As[cur][k][ty * 8];
            *(float4*)&ar[4] = *(const float4*)&As[cur][k][ty * 8 + 4];
            ull b2[4];
            const ull* bp = (const ull*)&Bs[cur][k][tx * 8];
            b2[0] = bp[0]; b2[1] = bp[1]; b2[2] = bp[2]; b2[3] = bp[3];
            ull a2[8];
#pragma unroll
            for (int i = 0; i < 8; i++) a2[i] = splat2(ar[i]);
#pragma unroll
            for (int i = 0; i < 8; i++)
#pragma unroll
                for (int p = 0; p < 4; p++)
                    acc[i][p] = fma2(a2[i], b2[p], acc[i][p]);
        }
        if (more) {
            int alt = cur ^ 1;
            As[alt][acol + 0][arow] = av.x;
            As[alt][acol + 1][arow] = av.y;
            As[alt][acol + 2][arow] = av.z;
            As[alt][acol + 3][arow] = av.w;
            *(float4*)&Bs[alt][brow][bcol] = bv;
        }
        __syncthreads();
    }

    // epilogue
#pragma unroll
    for (int i = 0; i < 8; i++) {
        int row = by * 128 + ty * 8 + i;
        int col = bx * 128 + tx * 8;
        float* Cp = C + (size_t)row * N + col;
        const float* bp = bias + col;
        float c0, c1, c2, c3, c4, c5, c6, c7;
        unpack2(acc[i][0], c0, c1);
        unpack2(acc[i][1], c2, c3);
        unpack2(acc[i][2], c4, c5);
        unpack2(acc[i][3], c6, c7);
        float4 o0, o1;
        o0.x = c0 + bp[0]; o0.y = c1 + bp[1];
        o0.z = c2 + bp[2]; o0.w = c3 + bp[3];
        o1.x = c4 + bp[4]; o1.y = c5 + bp[5];
        o1.z = c6 + bp[6]; o1.w = c7 + bp[7];
        *(float4*)Cp = o0;
        *(float4*)(Cp + 4) = o1;
    }
}

// ---------------- fused LSTM timestep v3 ----------------
// 128 blocks; block owns 8 hidden units (32 gate-columns).
// K=1024 processed as 4 chunks of 256, double-buffered via cp.async.
// Weights hit L2 exactly once per step (smem-staged), 8x8 microtile FFMA2.
//
// smem: ws[2][256][32] (64KB) + hs[2][256][36] (72KB) = 136KB
// reduction buffer (64KB) aliases ws after compute.
#define WS_STRIDE (256 * 32)
#define HS_STRIDE (256 * 36)
#define LSTM_SMEM ((2 * WS_STRIDE + 2 * HS_STRIDE) * 4)

__global__ __launch_bounds__(256, 1) void lstm_step3(
    const float* __restrict__ gx,     // [BT][G]
    const float* __restrict__ Wh,     // [H][G]
    const float* __restrict__ h_in,   // [B][H]
    float* __restrict__ h_out,        // [B][H]
    float* __restrict__ c_st,         // [B][H]
    float* __restrict__ hseq,         // [BT][H]
    int t)
{
    extern __shared__ float sm[];
    float* ws = sm;                        // [2][256][32]
    float* hsb = sm + 2 * WS_STRIDE;       // [2][256][36]
    float* red = sm;                       // aliases ws after compute

    int tid = threadIdx.x;
    int s = tid >> 4;        // k-slice 0..15
    int tile = tid & 15;
    int bg = tile >> 2;      // batch group 0..3 (8 batches)
    int g = tile & 3;        // gate 0..3
    int j0 = blockIdx.x * 8;

    const float4* h4 = (const float4*)h_in;   // rows of 256 float4

    // staging index precompute
    // weights: f = tid + l*256 -> k=f>>3, wg=(f>>1)&3, half=f&1
    // h:       q = tid + l*256 -> b=q>>6, k4=q&63

    // ---- prologue: stage chunk 0 into buffer 0 ----
#pragma unroll
    for (int l = 0; l < 8; l++) {
        int f = tid + l * 256;
        int k = f >> 3, wg = (f >> 1) & 3, half = f & 1;
        cp_async16(&ws[k * 32 + wg * 8 + half * 4],
                   Wh + (size_t)k * G + wg * H + j0 + half * 4);
    }
    cp_async_commit();
    {
        float4 hreg[8];
#pragma unroll
        for (int l = 0; l < 8; l++) {
            int q = tid + l * 256;
            hreg[l] = h4[(q >> 6) * 256 + (q & 63)];
        }
#pragma unroll
        for (int l = 0; l < 8; l++) {
            int q = tid + l * 256;
            int b = q >> 6, kl = (q & 63) * 4;
            hsb[(kl + 0) * 36 + b] = hreg[l].x;
            hsb[(kl + 1) * 36 + b] = hreg[l].y;
            hsb[(kl + 2) * 36 + b] = hreg[l].z;
            hsb[(kl + 3) * 36 + b] = hreg[l].w;
        }
    }
    cp_async_wait_all();
    __syncthreads();

    ull acc[8][4];
#pragma unroll
    for (int i = 0; i < 8; i++)
#pragma unroll
        for (int p = 0; p < 4; p++) acc[i][p] = 0ull;

    for (int c = 0; c < 4; c++) {
        int d = c & 1;
        float4 hreg[8];
        bool more = (c < 3);
        if (more) {
            // issue next chunk weight cp.async into alt buffer
            float* wsn = ws + (d ^ 1) * WS_STRIDE;
#pragma unroll
            for (int l = 0; l < 8; l++) {
                int f = tid + l * 256;
                int k = f >> 3, wg = (f >> 1) & 3, half = f & 1;
                cp_async16(&wsn[k * 32 + wg * 8 + half * 4],
                           Wh + (size_t)(c * 256 + 256 + k) * G + wg * H + j0 + half * 4);
            }
            cp_async_commit();
#pragma unroll
            for (int l = 0; l < 8; l++) {
                int q = tid + l * 256;
                hreg[l] = h4[(q >> 6) * 256 + (c + 1) * 64 + (q & 63)];
            }
        }

        // ---- compute this chunk ----
        const float* wsc = ws + d * WS_STRIDE;
        const float* hsc = hsb + d * HS_STRIDE;
#pragma unroll 4
        for (int kk = 0; kk < 16; kk++) {
            int k = kk * 16 + s;
            float hv[8];
            *(float4*)&hv[0] = *(const float4*)&hsc[k * 36 + bg * 8];
            *(float4*)&hv[4] = *(const float4*)&hsc[k * 36 + bg * 8 + 4];
            ull w2[4];
            const ull* wp = (const ull*)&wsc[k * 32 + g * 8];
            w2[0] = wp[0]; w2[1] = wp[1]; w2[2] = wp[2]; w2[3] = wp[3];
            ull a2[8];
#pragma unroll
            for (int i = 0; i < 8; i++) a2[i] = splat2(hv[i]);
#pragma unroll
            for (int i = 0; i < 8; i++)
#pragma unroll
                for (int p = 0; p < 4; p++)
                    acc[i][p] = fma2(a2[i], w2[p], acc[i][p]);
        }

        if (more) {
            float* hsn = hsb + (d ^ 1) * HS_STRIDE;
#pragma unroll
            for (int l = 0; l < 8; l++) {
                int q = tid + l * 256;
                int b = q >> 6, kl = (q & 63) * 4;
                hsn[(kl + 0) * 36 + b] = hreg[l].x;
                hsn[(kl + 1) * 36 + b] = hreg[l].y;
                hsn[(kl + 2) * 36 + b] = hreg[l].z;
                hsn[(kl + 3) * 36 + b] = hreg[l].w;
            }
        }
        cp_async_wait_all();
        __syncthreads();
    }

    // ---- split-k reduction via smem (aliases ws) ----
    // red[s][bg][g][i][jj], 16*4*4*64 floats = 64KB
    {
        int base = ((s * 4 + bg) * 4 + g) * 64;
#pragma unroll
        for (int i = 0; i < 8; i++)
#pragma unroll
            for (int p = 0; p < 4; p++) {
                float lo, hi;
                unpack2(acc[i][p], lo, hi);
                red[base + i * 8 + 2 * p] = lo;
                red[base + i * 8 + 2 * p + 1] = hi;
            }
    }
    __syncthreads();

    // ---- final reduce + cell update: thread -> (b, jj) ----
    {
        int b = tid >> 3;
        int jj = tid & 7;
        float gate[4] = {0.f, 0.f, 0.f, 0.f};
        int bgi = b >> 3, ii = b & 7;
#pragma unroll
        for (int ss = 0; ss < 16; ss++) {
#pragma unroll
            for (int gg = 0; gg < 4; gg++)
                gate[gg] += red[((ss * 4 + bgi) * 4 + gg) * 64 + ii * 8 + jj];
        }
        int jg = j0 + jj;
        const float* gxr = gx + (size_t)(b * T + t) * G;
        float vi = gate[0] + gxr[0 * H + jg];
        float vj = gate[1] + gxr[1 * H + jg];
        float vf = gate[2] + gxr[2 * H + jg];
        float vo = gate[3] + gxr[3 * H + jg];
        float cold = c_st[b * H + jg];
        float si = 1.f / (1.f + expf(-vi));
        float sf = 1.f / (1.f + expf(-(vf + 1.f)));
        float so = 1.f / (1.f + expf(-vo));
        float cnew = sf * cold + si * tanhf(vj);
        float hnew = so * tanhf(cnew);
        c_st[b * H + jg] = cnew;
        h_out[b * H + jg] = hnew;
        hseq[(size_t)(b * T + t) * H + jg] = hnew;
    }
}

// ---------------- launcher ----------------
extern "C" void kernel_launch(void* const* d_in, const int* in_sizes, int n_in,
                              void* d_out, int out_size)
{
    const int*   input_seq = (const int*)d_in[0];
    const float* emb = (const float*)d_in[1];
    const float* W0  = (const float*)d_in[2];
    const float* b0  = (const float*)d_in[3];
    const float* W1  = (const float*)d_in[4];
    const float* b1  = (const float*)d_in[5];
    const float* Wd  = (const float*)d_in[6];
    const float* bd  = (const float*)d_in[7];
    float* out = (float*)d_out;
    (void)in_sizes; (void)n_in; (void)out_size;

    float *xemb, *gx, *hs0, *hs1, *h0, *h1, *cbuf;
    cudaGetSymbolAddress((void**)&xemb, g_xemb);
    cudaGetSymbolAddress((void**)&gx,   g_gx);
    cudaGetSymbolAddress((void**)&hs0,  g_hseq0);
    cudaGetSymbolAddress((void**)&hs1,  g_hseq1);
    cudaGetSymbolAddress((void**)&h0,   g_h0);
    cudaGetSymbolAddress((void**)&h1,   g_h1);
    cudaGetSymbolAddress((void**)&cbuf, g_c);

    cudaFuncSetAttribute(lstm_step3, cudaFuncAttributeMaxDynamicSharedMemorySize, LSTM_SMEM);

    // 1) embedding
    embed_kernel<<<BT, 256>>>(input_seq, emb);

    // 2) layer-0 input-path gates
    dim3 gGX(G / 128, BT / 128);
    sgemm_bias2<<<gGX, 256>>>(xemb, W0, b0, gx, BT, G, E);

    // 3) layer-0 recurrence
    zero_state_kernel<<<(B * H + 255) / 256, 256>>>();
    for (int t = 0; t < T; t++) {
        float* hin  = (t & 1) ? h1 : h0;
        float* hout = (t & 1) ? h0 : h1;
        lstm_step3<<<128, 256, LSTM_SMEM>>>(gx, W0 + (size_t)E * G, hin, hout, cbuf, hs0, t);
    }

    // 4) layer-1 input-path gates
    sgemm_bias2<<<gGX, 256>>>(hs0, W1, b1, gx, BT, G, H);

    // 5) layer-1 recurrence
    zero_state_kernel<<<(B * H + 255) / 256, 256>>>();
    for (int t = 0; t < T; t++) {
        float* hin  = (t & 1) ? h1 : h0;
        float* hout = (t & 1) ? h0 : h1;
        lstm_step3<<<128, 256, LSTM_SMEM>>>(gx, W1 + (size_t)H * G, hin, hout, cbuf, hs1, t);
    }

    // 6) dense projection
    dim3 gOUT(V / 128, BT / 128);
    sgemm_bias2<<<gOUT, 256>>>(hs1, Wd, bd, out, BT, V, H);
}

// round 5
// speedup vs baseline: 1.2680x; 1.0348x over previous
#include <cuda_runtime.h>
#include <math.h>

#define B 32
#define T 128
#define BT 4096
#define E 1024
#define H 1024
#define G 4096
#define V 32000
#define NBLK 128

typedef unsigned long long ull;

// ---------------- packed f32x2 helpers ----------------
__device__ __forceinline__ ull fma2(ull a, ull b, ull c) {
    ull d;
    asm("fma.rn.f32x2 %0, %1, %2, %3;" : "=l"(d) : "l"(a), "l"(b), "l"(c));
    return d;
}
__device__ __forceinline__ ull splat2(float x) {
    ull d;
    asm("mov.b64 %0, {%1, %1};" : "=l"(d) : "f"(x));
    return d;
}
__device__ __forceinline__ void unpack2(ull v, float& lo, float& hi) {
    asm("mov.b64 {%0, %1}, %2;" : "=f"(lo), "=f"(hi) : "l"(v));
}

// ---------------- cp.async helpers ----------------
__device__ __forceinline__ void cp_async16(void* smem_ptr, const void* gptr) {
    unsigned s = (unsigned)__cvta_generic_to_shared(smem_ptr);
    asm volatile("cp.async.cg.shared.global [%0], [%1], 16;\n" :: "r"(s), "l"(gptr));
}
__device__ __forceinline__ void cp_async_commit() {
    asm volatile("cp.async.commit_group;\n");
}
__device__ __forceinline__ void cp_async_wait_all() {
    asm volatile("cp.async.wait_group 0;\n" ::: "memory");
}

// ---------------- acquire/release for grid barrier ----------------
__device__ __forceinline__ unsigned ld_acq(unsigned* p) {
    unsigned v;
    asm volatile("ld.acquire.gpu.u32 %0, [%1];" : "=r"(v) : "l"(p) : "memory");
    return v;
}
__device__ __forceinline__ void st_rel(unsigned* p, unsigned v) {
    asm volatile("st.release.gpu.u32 [%0], %1;" :: "l"(p), "r"(v) : "memory");
}

// ---------------- device scratch ----------------
__device__ __align__(16) float g_xemb[BT * E];
__device__ __align__(16) float g_gx[BT * G];
__device__ __align__(16) float g_hseq0[BT * H];
__device__ __align__(16) float g_hseq1[BT * H];
__device__ __align__(16) float g_h0[B * H];
__device__ __align__(16) float g_h1[B * H];
__device__ __align__(16) float g_c[B * H];
__device__ unsigned g_sync_count = 0;
__device__ unsigned g_sync_gen = 0;

// ---------------- embedding gather ----------------
__global__ void embed_kernel(const int* __restrict__ idx, const float* __restrict__ emb) {
    int row = blockIdx.x;
    int tok = idx[row];
    const float4* src = (const float4*)(emb + (size_t)tok * E);
    float4* dst = (float4*)(g_xemb + (size_t)row * E);
    dst[threadIdx.x] = src[threadIdx.x];
}

// ---------------- double-buffered FFMA2 SGEMM + bias ----------------
__global__ __launch_bounds__(256, 2) void sgemm_bias2(
    const float* __restrict__ A, const float* __restrict__ Bm,
    const float* __restrict__ bias, float* __restrict__ C,
    int M, int N, int K)
{
    __shared__ float As[2][8][128];
    __shared__ float Bs[2][8][128];
    int tid = threadIdx.x;
    int bx = blockIdx.x, by = blockIdx.y;
    int tx = tid & 15, ty = tid >> 4;

    const float* Ab = A + (size_t)by * 128 * K;
    const float* Bb = Bm + (size_t)bx * 128;

    int arow = tid >> 1, acol = (tid & 1) * 4;
    int brow = tid >> 5, bcol = (tid & 31) * 4;

    ull acc[8][4];
#pragma unroll
    for (int i = 0; i < 8; i++)
#pragma unroll
        for (int p = 0; p < 4; p++) acc[i][p] = 0ull;

    {
        float4 av = *(const float4*)(Ab + (size_t)arow * K + acol);
        float4 bv = *(const float4*)(Bb + (size_t)brow * N + bcol);
        As[0][acol + 0][arow] = av.x;
        As[0][acol + 1][arow] = av.y;
        As[0][acol + 2][arow] = av.z;
        As[0][acol + 3][arow] = av.w;
        *(float4*)&Bs[0][brow][bcol] = bv;
    }
    __syncthreads();

    int nk = K >> 3;
    for (int kt = 0; kt < nk; kt++) {
        int cur = kt & 1;
        float4 av, bv;
        bool more = (kt + 1 < nk);
        if (more) {
            av = *(const float4*)(Ab + (size_t)arow * K + (kt + 1) * 8 + acol);
            bv = *(const float4*)(Bb + (size_t)((kt + 1) * 8 + brow) * N + bcol);
        }
#pragma unroll
        for (int k = 0; k < 8; k++) {
            float ar[8];
            *(float4*)&ar[0] = *(const float4*)&As[cur][k][ty * 8];
            *(float4*)&ar[4] = *(const float4*)&As[cur][k][ty * 8 + 4];
            ull b2[4];
            const ull* bp = (const ull*)&Bs[cur][k][tx * 8];
            b2[0] = bp[0]; b2[1] = bp[1]; b2[2] = bp[2]; b2[3] = bp[3];
            ull a2[8];
#pragma unroll
            for (int i = 0; i < 8; i++) a2[i] = splat2(ar[i]);
#pragma unroll
            for (int i = 0; i < 8; i++)
#pragma unroll
                for (int p = 0; p < 4; p++)
                    acc[i][p] = fma2(a2[i], b2[p], acc[i][p]);
        }
        if (more) {
            int alt = cur ^ 1;
            As[alt][acol + 0][arow] = av.x;
            As[alt][acol + 1][arow] = av.y;
            As[alt][acol + 2][arow] = av.z;
            As[alt][acol + 3][arow] = av.w;
            *(float4*)&Bs[alt][brow][bcol] = bv;
        }
        __syncthreads();
    }

#pragma unroll
    for (int i = 0; i < 8; i++) {
        int row = by * 128 + ty * 8 + i;
        int col = bx * 128 + tx * 8;
        float* Cp = C + (size_t)row * N + col;
        const float* bp = bias + col;
        float c0, c1, c2, c3, c4, c5, c6, c7;
        unpack2(acc[i][0], c0, c1);
        unpack2(acc[i][1], c2, c3);
        unpack2(acc[i][2], c4, c5);
        unpack2(acc[i][3], c6, c7);
        float4 o0, o1;
        o0.x = c0 + bp[0]; o0.y = c1 + bp[1];
        o0.z = c2 + bp[2]; o0.w = c3 + bp[3];
        o1.x = c4 + bp[4]; o1.y = c5 + bp[5];
        o1.z = c6 + bp[6]; o1.w = c7 + bp[7];
        *(float4*)Cp = o0;
        *(float4*)(Cp + 4) = o1;
    }
}

// ---------------- persistent LSTM layer kernel ----------------
// 128 blocks (one per 8 hidden units), resident for all 128 timesteps.
// Weights (block's 32 gate-columns x 1024 k = 128KB) live in smem the whole
// kernel. Per step: stream h (32x1024) from L2 in 8 double-buffered chunks,
// FFMA2 microtile compute, split-k reduce via smem, fused cell update,
// software grid barrier.
//
// smem: wsm[1024][32] (128KB) | hb[2][128][36] (36KB) | red[8][32][32] (32KB)
#define WSM_F (1024 * 32)
#define HBUF_F (128 * 36)
#define RED_F (8 * 32 * 32)
#define LSTM_SMEM ((WSM_F + 2 * HBUF_F + RED_F) * 4)

__device__ __forceinline__ void grid_barrier(unsigned gen) {
    __threadfence();
    __syncthreads();
    if (threadIdx.x == 0) {
        if (atomicAdd(&g_sync_count, 1u) == NBLK - 1) {
            g_sync_count = 0;
            st_rel(&g_sync_gen, gen);
        } else {
            while (ld_acq(&g_sync_gen) != gen) { }
        }
    }
    __syncthreads();
}

__global__ __launch_bounds__(256, 1) void lstm_persist(
    const float* __restrict__ gx,     // [BT][G]
    const float* __restrict__ Wh,     // [H][G] recurrent weights
    float* __restrict__ h0g,          // [B][H] ping
    float* __restrict__ h1g,          // [B][H] pong
    float* __restrict__ c_st,         // [B][H]
    float* __restrict__ hseq)         // [BT][H]
{
    extern __shared__ float smf[];
    float* wsm = smf;                       // [k][32]: k*32 + g*8 + jj
    float* hb  = smf + WSM_F;               // [2][128][36]
    float* red = smf + WSM_F + 2 * HBUF_F;  // [s][elem][tile]

    int tid = threadIdx.x;
    int j0 = blockIdx.x * 8;

    unsigned base = 0;
    if (tid == 0) base = ld_acq(&g_sync_gen);

    // ---- load this block's weight slice into smem (once) ----
#pragma unroll
    for (int l = 0; l < 32; l++) {
        int f = tid + l * 256;
        int k = f >> 3, g = (f >> 1) & 3, hf = f & 1;
        cp_async16(&wsm[k * 32 + g * 8 + hf * 4],
                   Wh + (size_t)k * G + g * H + j0 + hf * 4);
    }
    cp_async_commit();

    // ---- zero own columns of h0 and c ----
    {
        int b = tid >> 3, jj = tid & 7;
        h0g[b * H + j0 + jj] = 0.f;
        c_st[b * H + j0 + jj] = 0.f;
    }
    cp_async_wait_all();
    grid_barrier(base + 1);

    // compute-thread mapping: warp s = k-slice, lane: bg = lane>>2, g = lane&3
    int s = tid >> 5;
    int lane = tid & 31;
    int bg = lane >> 2;
    int g = lane & 3;
    // cell-update mapping
    int eu = tid >> 3, bgu = tid & 7;
    int iu = eu >> 3, jju = eu & 7;
    int bu = bgu * 4 + iu;
    int jgu = j0 + jju;

    for (int t = 0; t < T; t++) {
        const float* hin = (t & 1) ? h1g : h0g;
        float* hout = (t & 1) ? h0g : h1g;
        const float4* h4 = (const float4*)hin;

        // stage chunk 0
        {
            float4 hreg[4];
#pragma unroll
            for (int l = 0; l < 4; l++) {
                int q = tid + l * 256;
                hreg[l] = h4[(q >> 5) * 256 + (q & 31)];
            }
#pragma unroll
            for (int l = 0; l < 4; l++) {
                int q = tid + l * 256;
                int b = q >> 5, kl = (q & 31) * 4;
                hb[(kl + 0) * 36 + b] = hreg[l].x;
                hb[(kl + 1) * 36 + b] = hreg[l].y;
                hb[(kl + 2) * 36 + b] = hreg[l].z;
                hb[(kl + 3) * 36 + b] = hreg[l].w;
            }
        }
        __syncthreads();

        ull acc[4][4];
#pragma unroll
        for (int i = 0; i < 4; i++)
#pragma unroll
            for (int p = 0; p < 4; p++) acc[i][p] = 0ull;

        for (int c = 0; c < 8; c++) {
            int d = c & 1;
            float4 hreg[4];
            bool more = (c < 7);
            if (more) {
#pragma unroll
                for (int l = 0; l < 4; l++) {
                    int q = tid + l * 256;
                    hreg[l] = h4[(q >> 5) * 256 + (c + 1) * 32 + (q & 31)];
                }
            }

            const float* hs = hb + d * HBUF_F + s * 36 + bg * 4;
            const float* wp = wsm + (c * 128 + s) * 32 + g * 8;
#pragma unroll 8
            for (int kk = 0; kk < 16; kk++) {
                float4 hv = *(const float4*)&hs[kk * (8 * 36)];
                ull w2[4];
                const ull* wq = (const ull*)&wp[kk * 256];
                w2[0] = wq[0]; w2[1] = wq[1]; w2[2] = wq[2]; w2[3] = wq[3];
                ull a0 = splat2(hv.x), a1 = splat2(hv.y);
                ull a2v = splat2(hv.z), a3 = splat2(hv.w);
#pragma unroll
                for (int p = 0; p < 4; p++) {
                    acc[0][p] = fma2(a0, w2[p], acc[0][p]);
                    acc[1][p] = fma2(a1, w2[p], acc[1][p]);
                    acc[2][p] = fma2(a2v, w2[p], acc[2][p]);
                    acc[3][p] = fma2(a3, w2[p], acc[3][p]);
                }
            }

            if (more) {
                float* hn = hb + (d ^ 1) * HBUF_F;
#pragma unroll
                for (int l = 0; l < 4; l++) {
                    int q = tid + l * 256;
                    int b = q >> 5, kl = (q & 31) * 4;
                    hn[(kl + 0) * 36 + b] = hreg[l].x;
                    hn[(kl + 1) * 36 + b] = hreg[l].y;
                    hn[(kl + 2) * 36 + b] = hreg[l].z;
                    hn[(kl + 3) * 36 + b] = hreg[l].w;
                }
            }
            __syncthreads();
        }

        // split-k reduction: red[s][elem][tile], tile = lane = bg*4+g
#pragma unroll
        for (int i = 0; i < 4; i++)
#pragma unroll
            for (int p = 0; p < 4; p++) {
                float lo, hi;
                unpack2(acc[i][p], lo, hi);
                red[s * 1024 + (i * 8 + 2 * p) * 32 + lane] = lo;
                red[s * 1024 + (i * 8 + 2 * p + 1) * 32 + lane] = hi;
            }
        __syncthreads();

        // fused cell update: thread = (bgu, eu)
        {
            float4 gs = make_float4(0.f, 0.f, 0.f, 0.f);
#pragma unroll
            for (int ss = 0; ss < 8; ss++) {
                float4 v = *(const float4*)&red[ss * 1024 + eu * 32 + bgu * 4];
                gs.x += v.x; gs.y += v.y; gs.z += v.z; gs.w += v.w;
            }
            const float* gxr = gx + (size_t)(bu * T + t) * G;
            float vi = gs.x + gxr[0 * H + jgu];
            float vj = gs.y + gxr[1 * H + jgu];
            float vf = gs.z + gxr[2 * H + jgu];
            float vo = gs.w + gxr[3 * H + jgu];
            float cold = c_st[bu * H + jgu];
            float si = 1.f / (1.f + expf(-vi));
            float sf = 1.f / (1.f + expf(-(vf + 1.f)));
            float so = 1.f / (1.f + expf(-vo));
            float cnew = sf * cold + si * tanhf(vj);
            float hnew = so * tanhf(cnew);
            c_st[bu * H + jgu] = cnew;
            hout[bu * H + jgu] = hnew;
            hseq[(size_t)(bu * T + t) * H + jgu] = hnew;
        }

        grid_barrier(base + 2 + t);
    }
}

// ---------------- launcher ----------------
extern "C" void kernel_launch(void* const* d_in, const int* in_sizes, int n_in,
                              void* d_out, int out_size)
{
    const int*   input_seq = (const int*)d_in[0];
    const float* emb = (const float*)d_in[1];
    const float* W0  = (const float*)d_in[2];
    const float* b0  = (const float*)d_in[3];
    const float* W1  = (const float*)d_in[4];
    const float* b1  = (const float*)d_in[5];
    const float* Wd  = (const float*)d_in[6];
    const float* bd  = (const float*)d_in[7];
    float* out = (float*)d_out;
    (void)in_sizes; (void)n_in; (void)out_size;

    float *xemb, *gx, *hs0, *hs1, *h0, *h1, *cbuf;
    cudaGetSymbolAddress((void**)&xemb, g_xemb);
    cudaGetSymbolAddress((void**)&gx,   g_gx);
    cudaGetSymbolAddress((void**)&hs0,  g_hseq0);
    cudaGetSymbolAddress((void**)&hs1,  g_hseq1);
    cudaGetSymbolAddress((void**)&h0,   g_h0);
    cudaGetSymbolAddress((void**)&h1,   g_h1);
    cudaGetSymbolAddress((void**)&cbuf, g_c);

    cudaFuncSetAttribute(lstm_persist, cudaFuncAttributeMaxDynamicSharedMemorySize, LSTM_SMEM);

    // 1) embedding
    embed_kernel<<<BT, 256>>>(input_seq, emb);

    // 2) layer-0 input-path gates
    dim3 gGX(G / 128, BT / 128);
    sgemm_bias2<<<gGX, 256>>>(xemb, W0, b0, gx, BT, G, E);

    // 3) layer-0 recurrence (persistent)
    lstm_persist<<<NBLK, 256, LSTM_SMEM>>>(gx, W0 + (size_t)E * G, h0, h1, cbuf, hs0);

    // 4) layer-1 input-path gates
    sgemm_bias2<<<gGX, 256>>>(hs0, W1, b1, gx, BT, G, H);

    // 5) layer-1 recurrence (persistent)
    lstm_persist<<<NBLK, 256, LSTM_SMEM>>>(gx, W1 + (size_t)H * G, h0, h1, cbuf, hs1);

    // 6) dense projection
    dim3 gOUT(V / 128, BT / 128);
    sgemm_bias2<<<gOUT, 256>>>(hs1, Wd, bd, out, BT, V, H);
}